// round 8
// baseline (speedup 1.0000x reference)
#include <cuda_runtime.h>
#include <math.h>

#define IN_F   512
#define HID    256
#define BATCH  1024

// Column-major (transposed) edge masks.
// Layer 0: column i (512 cols), 8 words of 32 output bits:   g_cmask0[i*8 + w]
// Layer 1: column j (256 cols), 16 words stored INTERLEAVED: word pair for
//          warp w = outputs {32w..} and {32(w+8)..} at g_cmask1[j*16 + 2w +0/1]
__device__ unsigned int g_cmask0[IN_F * (HID / 32)];
__device__ unsigned int g_cmask1[HID  * (IN_F / 32)];

// ---------------------------------------------------------------------------
// Kernel 1: build TRANSPOSED bitmasks. One block = one 32(o) x 32(i) tile.
// ---------------------------------------------------------------------------
__global__ __launch_bounds__(1024)
void mask_kernel(const float* __restrict__ logits0, const float* __restrict__ u0,
                 const float* __restrict__ logits1, const float* __restrict__ u1)
{
    __shared__ unsigned char tile[32][33];

    const int ty   = threadIdx.x >> 5;   // local o
    const int lane = threadIdx.x & 31;   // local i
    int bl = blockIdx.x;

    const float* L; const float* U;
    int to, ti, IN, layer;
    if (bl < 128) {         // layer 0: o in [0,256), i in [0,512)
        L = logits0; U = u0; layer = 0;
        to = bl >> 4; ti = bl & 15; IN = IN_F;
    } else {                // layer 1: o in [0,512), i in [0,256)
        bl -= 128;
        L = logits1; U = u1; layer = 1;
        to = bl >> 3; ti = bl & 7;  IN = HID;
    }

    int o = to * 32 + ty;
    int i = ti * 32 + lane;
    int e = o * IN + i;                       // float2 index (E=2)

    float2 l = reinterpret_cast<const float2*>(L)[e];
    float2 u = reinterpret_cast<const float2*>(U)[e];

    const float LO = 1e-10f;
    const float HI = 1.0f - 1e-10f;
    float ca = fminf(fmaxf(u.x, LO), HI);
    float cb = fminf(fmaxf(u.y, LO), HI);

    bool pred;
    if (l.x == l.y) {
        pred = cb > ca;                       // gumbel monotone in clipped u
    } else {
        float g0 = -logf(-logf(ca));
        float g1 = -logf(-logf(cb));
        pred = (l.y + g1) > (l.x + g0);
    }

    tile[ty][lane] = pred ? 1 : 0;
    __syncthreads();

    unsigned bit = tile[lane][ty];
    unsigned bal = __ballot_sync(0xFFFFFFFFu, bit != 0);
    if (lane == 0) {
        int col = ti * 32 + ty;               // global input index
        if (layer == 0) {
            g_cmask0[col * 8 + to] = bal;     // to in [0,8)
        } else {
            g_cmask1[col * 16 + 2 * (to & 7) + (to >> 3)] = bal;
        }
    }
}

// ---------------------------------------------------------------------------
// 32x32 bit-matrix transpose across a warp (5 shfl_xor steps, literal masks).
// ---------------------------------------------------------------------------
__device__ __forceinline__ unsigned warp_bit_transpose(unsigned x, int lane)
{
    unsigned y;
    y = __shfl_xor_sync(0xFFFFFFFFu, x, 16);
    x = (lane & 16) ? ((x & 0xFFFF0000u) | ((y >> 16) & 0x0000FFFFu))
                    : ((x & 0x0000FFFFu) | ((y & 0x0000FFFFu) << 16));
    y = __shfl_xor_sync(0xFFFFFFFFu, x, 8);
    x = (lane & 8)  ? ((x & 0xFF00FF00u) | ((y >> 8) & 0x00FF00FFu))
                    : ((x & 0x00FF00FFu) | ((y & 0x00FF00FFu) << 8));
    y = __shfl_xor_sync(0xFFFFFFFFu, x, 4);
    x = (lane & 4)  ? ((x & 0xF0F0F0F0u) | ((y >> 4) & 0x0F0F0F0Fu))
                    : ((x & 0x0F0F0F0Fu) | ((y & 0x0F0F0F0Fu) << 4));
    y = __shfl_xor_sync(0xFFFFFFFFu, x, 2);
    x = (lane & 2)  ? ((x & 0xCCCCCCCCu) | ((y >> 2) & 0x33333333u))
                    : ((x & 0x33333333u) | ((y & 0x33333333u) << 2));
    y = __shfl_xor_sync(0xFFFFFFFFu, x, 1);
    x = (lane & 1)  ? ((x & 0xAAAAAAAAu) | ((y >> 1) & 0x55555555u))
                    : ((x & 0x55555555u) | ((y & 0x55555555u) << 1));
    return x;
}

// One window step of the first-hit walk for one output (exact tie rescan).
__device__ __forceinline__ void walk_step(
    float& v, unsigned& q, bool& done, bool& pend,
    unsigned hits, const unsigned* __restrict__ keys,   // skey + base
    const float* __restrict__ vals, unsigned lastb, bool isMin)
{
    unsigned scanb = 0;
    if (!done) {
        if (hits) {
            int p = __ffs(hits) - 1;
            unsigned k0 = keys[p];
            q = k0 >> 9;
            v = vals[k0 & 511u];
            done = true; pend = true;
            scanb = hits & (0xFFFFFFFEu << p);          // bits strictly > p
        }
    } else if (pend) {
        scanb = hits;
    }
    while (scanb) {                                      // same-bucket rescan
        int p2 = __ffs(scanb) - 1;
        scanb &= scanb - 1;
        unsigned k2 = keys[p2];
        if ((k2 >> 9) != q) { pend = false; break; }
        float u = vals[k2 & 511u];
        v = isMin ? fminf(v, u) : fmaxf(v, u);
    }
    if (pend) pend = (lastb == q);                       // bucket spills on?
}

// ---------------------------------------------------------------------------
// Kernel 2: fused two-layer evaluation, TWO batch rows per block, all phases
// interleaved over r (independent latency chains -> higher issue rate).
// Per row: counting sort + warp-local bit-parallel first-hit walk (round 6/7).
// ---------------------------------------------------------------------------
__global__ __launch_bounds__(256)
void row_kernel(const float* __restrict__ x, float* __restrict__ out)
{
    __shared__ unsigned cnt [2][IN_F];   // counts, then exclusive offsets
    __shared__ unsigned skey[2][IN_F];   // sorted keys: (bucket<<9)|idx
    __shared__ float    sval[2][IN_F];   // exact x rows
    __shared__ float    shv [2][HID];    // exact h rows
    __shared__ unsigned wsum[2][8];

    const int t    = threadIdx.x;        // 0..255
    const int lane = t & 31;
    const int w    = t >> 5;
    const int row0 = blockIdx.x * 2;

    // ===== layer 0 sort: counting sort of x (512 linear buckets), 2 rows ===
    float v0[2], v1[2];
#pragma unroll
    for (int r = 0; r < 2; r++) {
        cnt[r][t] = 0; cnt[r][t + 256] = 0;
        v0[r] = x[(row0 + r) * IN_F + t];
        v1[r] = x[(row0 + r) * IN_F + t + 256];
        sval[r][t] = v0[r]; sval[r][t + 256] = v1[r];
    }
    __syncthreads();

    int b0[2], b1[2]; unsigned r0[2], r1[2];
#pragma unroll
    for (int r = 0; r < 2; r++) {
        b0[r] = min((int)(v0[r] * 512.0f), 511);   // exact pow2 -> monotone
        b1[r] = min((int)(v1[r] * 512.0f), 511);
        r0[r] = atomicAdd(&cnt[r][b0[r]], 1u);
        r1[r] = atomicAdd(&cnt[r][b1[r]], 1u);
    }
    __syncthreads();

    unsigned sc_[2], s_[2], c0_[2];
#pragma unroll
    for (int r = 0; r < 2; r++) {
        unsigned c0 = cnt[r][2 * t], c1 = cnt[r][2 * t + 1];
        unsigned s = c0 + c1, sc = s;
#pragma unroll
        for (int d = 1; d < 32; d <<= 1) {
            unsigned o = __shfl_up_sync(0xFFFFFFFFu, sc, d);
            if (lane >= d) sc += o;
        }
        if (lane == 31) wsum[r][w] = sc;
        sc_[r] = sc; s_[r] = s; c0_[r] = c0;
    }
    __syncthreads();
#pragma unroll
    for (int r = 0; r < 2; r++) {
        unsigned ws = (lane < 8) ? wsum[r][lane] : 0u;
#pragma unroll
        for (int d = 1; d < 8; d <<= 1) {
            unsigned o = __shfl_up_sync(0xFFFFFFFFu, ws, d);
            if (lane >= d) ws += o;
        }
        unsigned wx = __shfl_sync(0xFFFFFFFFu, ws, (w == 0) ? 0 : (w - 1));
        if (w == 0) wx = 0;
        unsigned excl = wx + sc_[r] - s_[r];
        cnt[r][2 * t]     = excl;
        cnt[r][2 * t + 1] = excl + c0_[r];
    }
    __syncthreads();
#pragma unroll
    for (int r = 0; r < 2; r++) {
        skey[r][cnt[r][b0[r]] + r0[r]] = ((unsigned)b0[r] << 9) | (unsigned)t;
        skey[r][cnt[r][b1[r]] + r1[r]] = ((unsigned)b1[r] << 9) | (unsigned)(t + 256);
    }
    __syncthreads();

    // ===== layer 0 walk: warp w owns outputs 32w..32w+31, both rows ========
    float h[2] = {1.0f, 1.0f};
    {
        bool done[2] = {false, false}, pend[2] = {false, false};
        unsigned qb[2] = {0, 0};
        for (int base = 0; base < IN_F; base += 32) {
#pragma unroll
            for (int r = 0; r < 2; r++) {
                unsigned keyl  = skey[r][base + lane];
                unsigned lastb = __shfl_sync(0xFFFFFFFFu, keyl, 31) >> 9;
                unsigned col   = g_cmask0[(keyl & 511u) * 8 + w];
                unsigned hits  = warp_bit_transpose(col, lane);
                walk_step(h[r], qb[r], done[r], pend[r], hits,
                          &skey[r][base], sval[r], lastb, true);
            }
            if (__all_sync(0xFFFFFFFFu,
                           done[0] && !pend[0] && done[1] && !pend[1])) break;
        }
    }
    __syncthreads();                  // walks read skey/sval before reuse

    // ===== layer 1 sort: counting sort of h, LOG buckets, descending =======
#pragma unroll
    for (int r = 0; r < 2; r++) { shv[r][t] = h[r]; cnt[r][t] = 0; }
    __syncthreads();

    // bucket = clamp((hbits>>19)-1792, 0, 255): exp + top-4 mantissa bits,
    // monotone in h >= 0; h <= 1.0 -> bucket <= 240.
    int bd[2]; unsigned rr[2];
#pragma unroll
    for (int r = 0; r < 2; r++) {
        unsigned hb = __float_as_uint(h[r]);
        int bkt = min(max((int)(hb >> 19) - 1792, 0), 255);
        bd[r] = 255 - bkt;            // descending
        rr[r] = atomicAdd(&cnt[r][bd[r]], 1u);
    }
    __syncthreads();

    unsigned scn_[2], c_[2];
#pragma unroll
    for (int r = 0; r < 2; r++) {
        unsigned c = cnt[r][t], scn = c;
#pragma unroll
        for (int d = 1; d < 32; d <<= 1) {
            unsigned o = __shfl_up_sync(0xFFFFFFFFu, scn, d);
            if (lane >= d) scn += o;
        }
        if (lane == 31) wsum[r][w] = scn;
        scn_[r] = scn; c_[r] = c;
    }
    __syncthreads();
#pragma unroll
    for (int r = 0; r < 2; r++) {
        unsigned ws = (lane < 8) ? wsum[r][lane] : 0u;
#pragma unroll
        for (int d = 1; d < 8; d <<= 1) {
            unsigned o = __shfl_up_sync(0xFFFFFFFFu, ws, d);
            if (lane >= d) ws += o;
        }
        unsigned wx = __shfl_sync(0xFFFFFFFFu, ws, (w == 0) ? 0 : (w - 1));
        if (w == 0) wx = 0;
        cnt[r][t] = wx + scn_[r] - c_[r];
    }
    __syncthreads();
#pragma unroll
    for (int r = 0; r < 2; r++)
        skey[r][cnt[r][bd[r]] + rr[r]] = ((unsigned)bd[r] << 9) | (unsigned)t;
    __syncthreads();

    // ===== layer 1 walk: words a (o=t) and b (o=t+256), both rows ==========
    float ra[2] = {0.0f, 0.0f}, rb[2] = {0.0f, 0.0f};
    {
        bool da[2] = {false, false}, pa[2] = {false, false};
        bool db[2] = {false, false}, pb[2] = {false, false};
        unsigned qa[2] = {0, 0}, qv[2] = {0, 0};
        const uint2* __restrict__ cm1 = reinterpret_cast<const uint2*>(g_cmask1);
        for (int base = 0; base < HID; base += 32) {
#pragma unroll
            for (int r = 0; r < 2; r++) {
                unsigned keyl  = skey[r][base + lane];
                unsigned lastb = __shfl_sync(0xFFFFFFFFu, keyl, 31) >> 9;
                uint2 cw = cm1[(keyl & 511u) * 8 + w];       // one LDG.64
                unsigned hta = warp_bit_transpose(cw.x, lane);
                unsigned htb = warp_bit_transpose(cw.y, lane);
                walk_step(ra[r], qa[r], da[r], pa[r], hta,
                          &skey[r][base], shv[r], lastb, false);
                walk_step(rb[r], qv[r], db[r], pb[r], htb,
                          &skey[r][base], shv[r], lastb, false);
            }
            if (__all_sync(0xFFFFFFFFu,
                           da[0] && !pa[0] && db[0] && !pb[0] &&
                           da[1] && !pa[1] && db[1] && !pb[1])) break;
        }
    }

#pragma unroll
    for (int r = 0; r < 2; r++) {
        out[(row0 + r) * IN_F + t]       = ra[r];
        out[(row0 + r) * IN_F + t + 256] = rb[r];
    }
}

// ---------------------------------------------------------------------------
// kernel_launch: graph-capturable, allocation-free.
// Inputs: x, logits0, u0, logits1, u1. Output: float32 [1024,512].
// ---------------------------------------------------------------------------
extern "C" void kernel_launch(void* const* d_in, const int* in_sizes, int n_in,
                              void* d_out, int out_size)
{
    const float* x       = (const float*)d_in[0];
    const float* logits0 = (const float*)d_in[1];
    const float* u0      = (const float*)d_in[2];
    const float* logits1 = (const float*)d_in[3];
    const float* u1      = (const float*)d_in[4];
    float* out = (float*)d_out;

    mask_kernel<<<256, 1024>>>(logits0, u0, logits1, u1);
    row_kernel<<<BATCH / 2, 256>>>(x, out);
}

// round 9
// speedup vs baseline: 1.0917x; 1.0917x over previous
#include <cuda_runtime.h>
#include <math.h>

#define IN_F   512
#define HID    256
#define BATCH  1024

// Column-major (transposed) edge masks.
// Layer 0: column i (512 cols), 8 words of 32 output bits:   g_cmask0[i*8 + w]
// Layer 1: column j (256 cols), 16 words stored INTERLEAVED: word pair for
//          warp w = outputs {32w..} and {32(w+8)..} at g_cmask1[j*16 + 2w +0/1]
__device__ unsigned int g_cmask0[IN_F * (HID / 32)];
__device__ unsigned int g_cmask1[HID  * (IN_F / 32)];

// Per-half named barrier: half 0 -> bar 1, half 1 -> bar 2 (256 threads each).
#define HALF_BAR(h) asm volatile("bar.sync %0, 256;" :: "r"((h) + 1) : "memory")

// ---------------------------------------------------------------------------
// Kernel 1: build TRANSPOSED bitmasks. One block = one 32(o) x 32(i) tile.
// ---------------------------------------------------------------------------
__global__ __launch_bounds__(1024)
void mask_kernel(const float* __restrict__ logits0, const float* __restrict__ u0,
                 const float* __restrict__ logits1, const float* __restrict__ u1)
{
    __shared__ unsigned char tile[32][33];

    const int ty   = threadIdx.x >> 5;   // local o
    const int lane = threadIdx.x & 31;   // local i
    int bl = blockIdx.x;

    const float* L; const float* U;
    int to, ti, IN, layer;
    if (bl < 128) {         // layer 0: o in [0,256), i in [0,512)
        L = logits0; U = u0; layer = 0;
        to = bl >> 4; ti = bl & 15; IN = IN_F;
    } else {                // layer 1: o in [0,512), i in [0,256)
        bl -= 128;
        L = logits1; U = u1; layer = 1;
        to = bl >> 3; ti = bl & 7;  IN = HID;
    }

    int o = to * 32 + ty;
    int i = ti * 32 + lane;
    int e = o * IN + i;                       // float2 index (E=2)

    float2 l = reinterpret_cast<const float2*>(L)[e];
    float2 u = reinterpret_cast<const float2*>(U)[e];

    const float LO = 1e-10f;
    const float HI = 1.0f - 1e-10f;
    float ca = fminf(fmaxf(u.x, LO), HI);
    float cb = fminf(fmaxf(u.y, LO), HI);

    bool pred;
    if (l.x == l.y) {
        pred = cb > ca;                       // gumbel monotone in clipped u
    } else {
        float g0 = -logf(-logf(ca));
        float g1 = -logf(-logf(cb));
        pred = (l.y + g1) > (l.x + g0);
    }

    tile[ty][lane] = pred ? 1 : 0;
    __syncthreads();

    unsigned bit = tile[lane][ty];
    unsigned bal = __ballot_sync(0xFFFFFFFFu, bit != 0);
    if (lane == 0) {
        int col = ti * 32 + ty;               // global input index
        if (layer == 0) {
            g_cmask0[col * 8 + to] = bal;     // to in [0,8)
        } else {
            g_cmask1[col * 16 + 2 * (to & 7) + (to >> 3)] = bal;
        }
    }
}

// ---------------------------------------------------------------------------
// 32x32 bit-matrix transpose across a warp (5 shfl_xor steps, literal masks).
// ---------------------------------------------------------------------------
__device__ __forceinline__ unsigned warp_bit_transpose(unsigned x, int lane)
{
    unsigned y;
    y = __shfl_xor_sync(0xFFFFFFFFu, x, 16);
    x = (lane & 16) ? ((x & 0xFFFF0000u) | ((y >> 16) & 0x0000FFFFu))
                    : ((x & 0x0000FFFFu) | ((y & 0x0000FFFFu) << 16));
    y = __shfl_xor_sync(0xFFFFFFFFu, x, 8);
    x = (lane & 8)  ? ((x & 0xFF00FF00u) | ((y >> 8) & 0x00FF00FFu))
                    : ((x & 0x00FF00FFu) | ((y & 0x00FF00FFu) << 8));
    y = __shfl_xor_sync(0xFFFFFFFFu, x, 4);
    x = (lane & 4)  ? ((x & 0xF0F0F0F0u) | ((y >> 4) & 0x0F0F0F0Fu))
                    : ((x & 0x0F0F0F0Fu) | ((y & 0x0F0F0F0Fu) << 4));
    y = __shfl_xor_sync(0xFFFFFFFFu, x, 2);
    x = (lane & 2)  ? ((x & 0xCCCCCCCCu) | ((y >> 2) & 0x33333333u))
                    : ((x & 0x33333333u) | ((y & 0x33333333u) << 2));
    y = __shfl_xor_sync(0xFFFFFFFFu, x, 1);
    x = (lane & 1)  ? ((x & 0xAAAAAAAAu) | ((y >> 1) & 0x55555555u))
                    : ((x & 0x55555555u) | ((y & 0x55555555u) << 1));
    return x;
}

// One window step of the first-hit walk for one output (exact tie rescan).
__device__ __forceinline__ void walk_step(
    float& v, unsigned& q, bool& done, bool& pend,
    unsigned hits, const unsigned* __restrict__ keys,   // skey + base
    const float* __restrict__ vals, unsigned lastb, bool isMin)
{
    unsigned scanb = 0;
    if (!done) {
        if (hits) {
            int p = __ffs(hits) - 1;
            unsigned k0 = keys[p];
            q = k0 >> 9;
            v = vals[k0 & 511u];
            done = true; pend = true;
            scanb = hits & (0xFFFFFFFEu << p);          // bits strictly > p
        }
    } else if (pend) {
        scanb = hits;
    }
    while (scanb) {                                      // same-bucket rescan
        int p2 = __ffs(scanb) - 1;
        scanb &= scanb - 1;
        unsigned k2 = keys[p2];
        if ((k2 >> 9) != q) { pend = false; break; }
        float u = vals[k2 & 511u];
        v = isMin ? fminf(v, u) : fmaxf(v, u);
    }
    if (pend) pend = (lastb == q);                       // bucket spills on?
}

// ---------------------------------------------------------------------------
// Kernel 2: fused two-layer evaluation. 512 threads = TWO independent
// 256-thread halves, each owning one batch row with its own shared arrays
// and its own NAMED barrier (no cross-row coupling). Per half: counting sort
// + warp-local bit-parallel first-hit walk (identical to round-7 logic).
// ---------------------------------------------------------------------------
__global__ __launch_bounds__(512)
void row_kernel(const float* __restrict__ x, float* __restrict__ out)
{
    __shared__ unsigned cnt [2][IN_F];   // counts, then exclusive offsets
    __shared__ unsigned skey[2][IN_F];   // sorted keys: (bucket<<9)|idx
    __shared__ float    sval[2][IN_F];   // exact x rows
    __shared__ float    shv [2][HID];    // exact h rows
    __shared__ unsigned wsum[2][8];

    const int half = threadIdx.x >> 8;   // 0 or 1: which row this half owns
    const int t    = threadIdx.x & 255;  // 0..255 within the half
    const int lane = t & 31;
    const int w    = t >> 5;
    const int b    = blockIdx.x * 2 + half;

    unsigned* const cntH  = cnt[half];
    unsigned* const skeyH = skey[half];
    float*    const svalH = sval[half];
    float*    const shvH  = shv[half];

    // ============ layer 0 sort: counting sort of x (512 linear buckets) ====
    cntH[t] = 0; cntH[t + 256] = 0;
    float v0 = x[b * IN_F + t];
    float v1 = x[b * IN_F + t + 256];
    svalH[t] = v0; svalH[t + 256] = v1;
    HALF_BAR(half);

    int b0 = min((int)(v0 * 512.0f), 511);   // exact pow2 scaling -> monotone
    int b1 = min((int)(v1 * 512.0f), 511);
    unsigned r0 = atomicAdd(&cntH[b0], 1u);
    unsigned r1 = atomicAdd(&cntH[b1], 1u);
    HALF_BAR(half);

    // exclusive scan of 512 counts: thread t owns buckets 2t, 2t+1
    unsigned c0 = cntH[2 * t], c1 = cntH[2 * t + 1];
    unsigned s  = c0 + c1, sc = s;
#pragma unroll
    for (int d = 1; d < 32; d <<= 1) {
        unsigned o = __shfl_up_sync(0xFFFFFFFFu, sc, d);
        if (lane >= d) sc += o;
    }
    if (lane == 31) wsum[half][w] = sc;
    HALF_BAR(half);
    {
        unsigned ws = (lane < 8) ? wsum[half][lane] : 0u;
#pragma unroll
        for (int d = 1; d < 8; d <<= 1) {
            unsigned o = __shfl_up_sync(0xFFFFFFFFu, ws, d);
            if (lane >= d) ws += o;
        }
        unsigned wx = __shfl_sync(0xFFFFFFFFu, ws, (w == 0) ? 0 : (w - 1));
        if (w == 0) wx = 0;
        unsigned excl = wx + sc - s;
        cntH[2 * t]     = excl;
        cntH[2 * t + 1] = excl + c0;
    }
    HALF_BAR(half);

    skeyH[cntH[b0] + r0] = ((unsigned)b0 << 9) | (unsigned)t;
    skeyH[cntH[b1] + r1] = ((unsigned)b1 << 9) | (unsigned)(t + 256);
    HALF_BAR(half);

    // ===== layer 0 bit-parallel walk: warp w owns outputs 32w..32w+31 ======
    float h = 1.0f;                   // default: no selected edge
    {
        bool done = false, pend = false;
        unsigned qb = 0;
        for (int base = 0; base < IN_F; base += 32) {
            unsigned keyl  = skeyH[base + lane];
            unsigned lastb = __shfl_sync(0xFFFFFFFFu, keyl, 31) >> 9;
            unsigned col   = g_cmask0[(keyl & 511u) * 8 + w];
            unsigned hits  = warp_bit_transpose(col, lane);
            walk_step(h, qb, done, pend, hits, skeyH + base, svalH, lastb, true);
            if (__all_sync(0xFFFFFFFFu, done && !pend)) break;
        }
    }
    HALF_BAR(half);                   // walks read skey/sval before reuse

    // ====== layer 1 sort: counting sort of h, LOG buckets, descending ======
    shvH[t] = h;
    cntH[t] = 0;
    HALF_BAR(half);

    // bucket = clamp((hbits>>19)-1792, 0, 255): exp + top-4 mantissa bits,
    // monotone in h >= 0; h <= 1.0 -> bucket <= 240.
    unsigned hb  = __float_as_uint(h);
    int bkt = min(max((int)(hb >> 19) - 1792, 0), 255);
    int bd  = 255 - bkt;              // descending
    unsigned rr = atomicAdd(&cntH[bd], 1u);
    HALF_BAR(half);

    unsigned c = cntH[t], scn = c;
#pragma unroll
    for (int d = 1; d < 32; d <<= 1) {
        unsigned o = __shfl_up_sync(0xFFFFFFFFu, scn, d);
        if (lane >= d) scn += o;
    }
    if (lane == 31) wsum[half][w] = scn;
    HALF_BAR(half);
    {
        unsigned ws = (lane < 8) ? wsum[half][lane] : 0u;
#pragma unroll
        for (int d = 1; d < 8; d <<= 1) {
            unsigned o = __shfl_up_sync(0xFFFFFFFFu, ws, d);
            if (lane >= d) ws += o;
        }
        unsigned wx = __shfl_sync(0xFFFFFFFFu, ws, (w == 0) ? 0 : (w - 1));
        if (w == 0) wx = 0;
        cntH[t] = wx + scn - c;
    }
    HALF_BAR(half);

    skeyH[cntH[bd] + rr] = ((unsigned)bd << 9) | (unsigned)t;
    HALF_BAR(half);

    // == layer 1 walk: warp w owns output words for o=t (a) and o=t+256 (b) =
    float ra = 0.0f, rb = 0.0f;       // default: no selected edge
    {
        bool da = false, pa = false, db = false, pb = false;
        unsigned qa = 0, qv = 0;
        const uint2* __restrict__ cm1 = reinterpret_cast<const uint2*>(g_cmask1);
        for (int base = 0; base < HID; base += 32) {
            unsigned keyl  = skeyH[base + lane];
            unsigned lastb = __shfl_sync(0xFFFFFFFFu, keyl, 31) >> 9;
            uint2 cw = cm1[(keyl & 511u) * 8 + w];       // one LDG.64
            unsigned hta = warp_bit_transpose(cw.x, lane);
            unsigned htb = warp_bit_transpose(cw.y, lane);
            walk_step(ra, qa, da, pa, hta, skeyH + base, shvH, lastb, false);
            walk_step(rb, qv, db, pb, htb, skeyH + base, shvH, lastb, false);
            if (__all_sync(0xFFFFFFFFu, da && !pa && db && !pb)) break;
        }
    }

    out[b * IN_F + t]       = ra;
    out[b * IN_F + t + 256] = rb;
}

// ---------------------------------------------------------------------------
// kernel_launch: graph-capturable, allocation-free.
// Inputs: x, logits0, u0, logits1, u1. Output: float32 [1024,512].
// ---------------------------------------------------------------------------
extern "C" void kernel_launch(void* const* d_in, const int* in_sizes, int n_in,
                              void* d_out, int out_size)
{
    const float* x       = (const float*)d_in[0];
    const float* logits0 = (const float*)d_in[1];
    const float* u0      = (const float*)d_in[2];
    const float* logits1 = (const float*)d_in[3];
    const float* u1      = (const float*)d_in[4];
    float* out = (float*)d_out;

    mask_kernel<<<256, 1024>>>(logits0, u0, logits1, u1);
    row_kernel<<<BATCH / 2, 512>>>(x, out);
}